// round 12
// baseline (speedup 1.0000x reference)
#include <cuda_runtime.h>
#include <cstdint>

// InstantNGP: hash-grid encode + MLP 32->64->64->3 via warp-level fp16 mma.sync
// m16n8k16 (f32 accumulate). Round-12 = R11 with layer-1 restructured nt-outer:
// pack all A k-blocks first (layer0 C dies), then per-nt 4-reg accumulator
// feeding the W2 partial dot immediately. Peak regs ~-30 -> 5 CTAs/SM.

namespace {

constexpr int S_DIM   = 1024;
constexpr int NPTS    = S_DIM * S_DIM;
constexpr int TBL     = 1 << 19;

constexpr int WARPS   = 4;
constexpr int THREADS = WARPS * 32;
constexpr int TILE    = 16;               // points per warp-tile
constexpr int TPW     = 8;                // tiles per warp
constexpr int PPW     = TILE * TPW;       // 128 points per warp
constexpr int GRID    = NPTS / (PPW * WARPS);   // 2048
constexpr int ESTRIDE = 20;               // uint32 per enc row (swizzled, conflict-free)
constexpr float ESCALE   = 256.0f;        // 2^8: lift enc out of fp16 subnormal range
constexpr float ESCALE_I = 1.0f / 256.0f;

__device__ __forceinline__ uint32_t f16x2(float lo, float hi) {
    uint32_t r;
    asm("cvt.rn.f16x2.f32 %0, %1, %2;" : "=r"(r) : "f"(hi), "f"(lo));
    return r;
}

__device__ __forceinline__ int eidx(int row, int col) {
    return row * ESTRIDE + (col ^ ((row >> 3) << 1));
}

__device__ __forceinline__ void mma16(float* d,
                                      uint32_t a0, uint32_t a1, uint32_t a2, uint32_t a3,
                                      uint32_t b0, uint32_t b1) {
    asm volatile(
        "mma.sync.aligned.m16n8k16.row.col.f32.f16.f16.f32 "
        "{%0,%1,%2,%3},{%4,%5,%6,%7},{%8,%9},{%0,%1,%2,%3};"
        : "+f"(d[0]), "+f"(d[1]), "+f"(d[2]), "+f"(d[3])
        : "r"(a0), "r"(a1), "r"(a2), "r"(a3), "r"(b0), "r"(b1));
}

__global__ __launch_bounds__(THREADS, 5) void ngp_mma_kernel(
    const float2* __restrict__ xy,
    const float2* __restrict__ tab,
    const float*  __restrict__ W0,     // (32, 64) [k][n]
    const float*  __restrict__ W1,     // (64, 64) [k][n]
    const float*  __restrict__ W2,     // (64, 3)
    float*        __restrict__ out)    // (3, S, S)
{
    __shared__ uint2    w0f[2 * 8 * 32];               // 4 KB  B frags layer0 (fp16)
    __shared__ uint2    w1f[4 * 8 * 32];               // 8 KB  B frags layer1 (fp16)
    __shared__ float    w2s[3 * 64];                   // packed [j][c], pre-scaled
    __shared__ uint32_t scratch[WARPS][TILE * ESTRIDE];  // 5 KB enc (fp16x2)

    const int tid = threadIdx.x;

    // ---- stage weights in fragment order (once per CTA) ----
    for (int i = tid; i < 2 * 8 * 32; i += THREADS) {
        const int kk = i >> 8, nt = (i >> 5) & 7, ln = i & 31;
        const int t = ln & 3, g = ln >> 2, n = nt * 8 + g;
        const int kb = 16 * kk + 2 * t;
        w0f[i] = make_uint2(f16x2(W0[kb * 64 + n],       W0[(kb + 1) * 64 + n]),
                            f16x2(W0[(kb + 8) * 64 + n], W0[(kb + 9) * 64 + n]));
    }
    for (int i = tid; i < 4 * 8 * 32; i += THREADS) {
        const int kk = i >> 8, nt = (i >> 5) & 7, ln = i & 31;
        const int t = ln & 3, g = ln >> 2, n = nt * 8 + g;
        const int kb = 16 * kk + 2 * t;
        w1f[i] = make_uint2(f16x2(W1[kb * 64 + n],       W1[(kb + 1) * 64 + n]),
                            f16x2(W1[(kb + 8) * 64 + n], W1[(kb + 9) * 64 + n]));
    }
    for (int i = tid; i < 3 * 64; i += THREADS) {
        const int j = i >> 6, c = i & 63;
        w2s[i] = W2[c * 3 + j] * ESCALE_I;   // undo enc scaling here
    }
    __syncthreads();

    const int wid  = tid >> 5;
    const int lane = tid & 31;
    const int t    = lane & 3;          // threadIDInGroup
    const int g    = lane >> 2;         // groupID (row within 8)
    const int h    = lane >> 4;         // level parity for encode
    const int pl   = lane & 15;         // point within tile for encode
    uint32_t* buf  = scratch[wid];
    const int wg   = blockIdx.x * WARPS + wid;

    // floor(16 * 1.5^l): even levels / odd levels
    const int res_e[8] = {16, 36, 81, 182, 410, 922, 2075, 4670};
    const int res_o[8] = {24, 54, 121, 273, 615, 1383, 3113, 7006};

    for (int tile = 0; tile < TPW; tile++) {
        const int tb = wg * PPW + tile * TILE;
        __syncwarp();

        // ---- encode: point pl, levels 2*lp + h; store fp16x2 (f0,f1)*2^8 ----
        const float2 p = __ldg(&xy[tb + pl]);
        const float c0 = p.x, c1 = p.y;
#pragma unroll
        for (int lp = 0; lp < 8; lp++) {
            const int res   = h ? res_o[lp] : res_e[lp];
            const int level = 2 * lp + h;
            const bool dense = (lp < 5);   // levels 0..9 dense, 10..15 hashed

            const float fres = (float)res;
            const float px = c0 * fres;
            const float py = c1 * fres;
            const float fx = floorf(px);
            const float fy = floorf(py);
            const float wx = px - fx;
            const float wy = py - fy;
            const int ix = (int)fx;
            const int iy = (int)fy;

            int i00, i01, i10, i11;
            if (dense) {
                const int r1 = res + 1;
                i00 = ix + iy * r1;
                i01 = i00 + r1;
                i10 = i00 + 1;
                i11 = i01 + 1;
            } else {
                const uint32_t P = 2654435761u;
                const uint32_t ux = (uint32_t)ix;
                const uint32_t uy = (uint32_t)iy;
                const uint32_t hy0 = uy * P;
                const uint32_t hy1 = (uy + 1u) * P;
                i00 = (int)((ux        ^ hy0) & (uint32_t)(TBL - 1));
                i01 = (int)((ux        ^ hy1) & (uint32_t)(TBL - 1));
                i10 = (int)(((ux + 1u) ^ hy0) & (uint32_t)(TBL - 1));
                i11 = (int)(((ux + 1u) ^ hy1) & (uint32_t)(TBL - 1));
            }

            const float2* lt = tab + (size_t)level * TBL;
            const float2 a00 = __ldg(lt + i00);
            const float2 a01 = __ldg(lt + i01);
            const float2 a10 = __ldg(lt + i10);
            const float2 a11 = __ldg(lt + i11);

            const float w00 = (1.0f - wx) * (1.0f - wy);
            const float w01 = (1.0f - wx) * wy;
            const float w10 = wx * (1.0f - wy);
            const float w11 = wx * wy;

            const float f0 = a00.x * w00 + a01.x * w01 + a10.x * w10 + a11.x * w11;
            const float f1 = a00.y * w00 + a01.y * w01 + a10.y * w10 + a11.y * w11;

            buf[eidx(pl, level)] = f16x2(f0 * ESCALE, f1 * ESCALE);
        }
        __syncwarp();

        // ---- layer 0: (16x32) @ (32x64), m16n8k16, 2 K-blocks x 8 N-tiles ----
        float C[8][4];
#pragma unroll
        for (int nt = 0; nt < 8; nt++)
#pragma unroll
            for (int j = 0; j < 4; j++) C[nt][j] = 0.0f;

#pragma unroll
        for (int kk = 0; kk < 2; kk++) {
            const uint32_t a0 = buf[eidx(g,     8 * kk + t)];
            const uint32_t a1 = buf[eidx(g + 8, 8 * kk + t)];
            const uint32_t a2 = buf[eidx(g,     8 * kk + t + 4)];
            const uint32_t a3 = buf[eidx(g + 8, 8 * kk + t + 4)];
#pragma unroll
            for (int nt = 0; nt < 8; nt++) {
                const uint2 b = w0f[(kk * 8 + nt) * 32 + lane];
                mma16(C[nt], a0, a1, a2, a3, b.x, b.y);
            }
        }

        // ---- pack all layer-1 A fragments (C dies here) ----
        uint32_t A[4][4];
#pragma unroll
        for (int kk = 0; kk < 4; kk++) {
            A[kk][0] = f16x2(fmaxf(C[2 * kk][0], 0.0f),     fmaxf(C[2 * kk][1], 0.0f));
            A[kk][1] = f16x2(fmaxf(C[2 * kk][2], 0.0f),     fmaxf(C[2 * kk][3], 0.0f));
            A[kk][2] = f16x2(fmaxf(C[2 * kk + 1][0], 0.0f), fmaxf(C[2 * kk + 1][1], 0.0f));
            A[kk][3] = f16x2(fmaxf(C[2 * kk + 1][2], 0.0f), fmaxf(C[2 * kk + 1][3], 0.0f));
        }

        // ---- layer 1 (nt-outer) fused with epilogue: 4-reg accumulator ----
        float acc[2][3] = {{0.f, 0.f, 0.f}, {0.f, 0.f, 0.f}};
#pragma unroll
        for (int nt = 0; nt < 8; nt++) {
            float C1[4] = {0.f, 0.f, 0.f, 0.f};
#pragma unroll
            for (int kk = 0; kk < 4; kk++) {
                const uint2 b = w1f[(kk * 8 + nt) * 32 + lane];
                mma16(C1, A[kk][0], A[kk][1], A[kk][2], A[kk][3], b.x, b.y);
            }
            const int cA = nt * 8 + 2 * t;
            float2 w[3];
#pragma unroll
            for (int j = 0; j < 3; j++)
                w[j] = *reinterpret_cast<const float2*>(&w2s[j * 64 + cA]);
            const float vA0 = fmaxf(C1[0], 0.0f);
            const float vB0 = fmaxf(C1[1], 0.0f);
            const float vA1 = fmaxf(C1[2], 0.0f);
            const float vB1 = fmaxf(C1[3], 0.0f);
#pragma unroll
            for (int j = 0; j < 3; j++) {
                acc[0][j] += vA0 * w[j].x + vB0 * w[j].y;
                acc[1][j] += vA1 * w[j].x + vB1 * w[j].y;
            }
        }
#pragma unroll
        for (int r = 0; r < 2; r++)
#pragma unroll
            for (int j = 0; j < 3; j++) {
                float v = acc[r][j];
                v += __shfl_xor_sync(0xffffffffu, v, 1);
                v += __shfl_xor_sync(0xffffffffu, v, 2);
                acc[r][j] = v;
            }
        if (t == 0) {
#pragma unroll
            for (int r = 0; r < 2; r++) {
                const int pid = tb + g + 8 * r;
#pragma unroll
                for (int j = 0; j < 3; j++) out[j * NPTS + pid] = acc[r][j];
            }
        }
    }
}

}  // namespace

extern "C" void kernel_launch(void* const* d_in, const int* in_sizes, int n_in,
                              void* d_out, int out_size) {
    (void)in_sizes; (void)n_in; (void)out_size;
    const float2* xy  = (const float2*)d_in[0];
    const float2* tab = (const float2*)d_in[1];
    const float*  W0  = (const float*)d_in[2];
    const float*  W1  = (const float*)d_in[3];
    const float*  W2  = (const float*)d_in[4];
    float* out = (float*)d_out;

    ngp_mma_kernel<<<GRID, THREADS>>>(xy, tab, W0, W1, W2, out);
}